// round 14
// baseline (speedup 1.0000x reference)
#include <cuda_runtime.h>

// N=8192, D=64, H=256
//   h  = tanh(y @ W1 + t*wt + b1)      [N,H]
//   dy = h @ W2 + b2                   [N,D]
//   div_i = sum_j (1-h_ij^2) * s_j,  s_j = sum_d W1[d,j]*W2[j,d]
//   out = [dy, -div]  -> [N, 65] float32

#define NN 8192
#define DD 64
#define HH 256
#define MT 32           // rows per CTA
#define NT 512          // threads per CTA (8 warps/SMSP at 2 CTAs/SM)
#define Y2P 18          // y pair-pitch (u64 units): 16 pairs + 2 pad

typedef unsigned long long u64;

__device__ float g_s[HH];   // s_j from prep kernel

__device__ __forceinline__ u64 pack2(float a, float b) {
    u64 r; asm("mov.b64 %0, {%1, %2};" : "=l"(r) : "f"(a), "f"(b)); return r;
}
__device__ __forceinline__ void unpack2(u64 v, float& a, float& b) {
    asm("mov.b64 {%0, %1}, %2;" : "=f"(a), "=f"(b) : "l"(v));
}
__device__ __forceinline__ u64 fma2(u64 a, u64 b, u64 c) {
    u64 d; asm("fma.rn.f32x2 %0, %1, %2, %3;" : "=l"(d) : "l"(a), "l"(b), "l"(c)); return d;
}
__device__ __forceinline__ u64 add2(u64 a, u64 b) {
    u64 d; asm("add.rn.f32x2 %0, %1, %2;" : "=l"(d) : "l"(a), "l"(b)); return d;
}
__device__ __forceinline__ float tanh_fast(float x) {
    float e = __expf(2.0f * x);
    return 1.0f - __fdividef(2.0f, e + 1.0f);
}

// ---------------- prep: s_j = sum_d W1[d,j]*W2[j,d], fully coalesced ----------------
__global__ void __launch_bounds__(128) ode_prep(
    const float* __restrict__ W1, const float* __restrict__ W2)
{
    __shared__ float w2s[32][65];
    __shared__ float red[4][32];
    const int t  = threadIdx.x;
    const int j0 = blockIdx.x * 32;

    const float4* src = (const float4*)(W2 + (size_t)j0 * DD);
    for (int i = t; i < 512; i += 128) {
        float4 v = src[i];
        int jl = i >> 4, d0 = (i & 15) << 2;
        w2s[jl][d0 + 0] = v.x; w2s[jl][d0 + 1] = v.y;
        w2s[jl][d0 + 2] = v.z; w2s[jl][d0 + 3] = v.w;
    }
    __syncthreads();

    const int jl = t & 31, dq = t >> 5;
    float p = 0.f;
    #pragma unroll
    for (int i = 0; i < 16; i++) {
        int d = dq * 16 + i;
        p = fmaf(W1[d * HH + j0 + jl], w2s[jl][d], p);
    }
    red[dq][jl] = p;
    __syncthreads();
    if (t < 32)
        g_s[j0 + t] = red[0][t] + red[1][t] + red[2][t] + red[3][t];
}

// ---------------- main ----------------
__global__ void __launch_bounds__(NT, 2) ode_main(
    const float* __restrict__ tt, const float* __restrict__ y,
    const float* __restrict__ W1, const float* __restrict__ b1,
    const float* __restrict__ wt, const float* __restrict__ W2,
    const float* __restrict__ b2, float* __restrict__ out)
{
    __shared__ __align__(16) float h_s[HH * MT];     // [j][r], pitch 32: 32KB
    __shared__ __align__(16) u64   y2[DD * Y2P];     // row-pairs y2[k][rp]: 9KB; later psum
    __shared__ float c_s[HH];
    __shared__ float s_s[HH];
    __shared__ float b2_s[DD];
    __shared__ float divp[16 * MT];

    const int tid  = threadIdx.x;
    const int row0 = blockIdx.x * MT;

    // constants (coalesced)
    if (tid < HH) {
        c_s[tid] = fmaf(tt[0], wt[tid], b1[tid]);
        s_s[tid] = g_s[tid];
    }
    if (tid >= HH && tid < HH + DD) b2_s[tid - HH] = b2[tid - HH];

    // ---- stage y as row-pairs: one float4 LDG per thread, scalar half-writes ----
    {
        const int r = tid >> 4, kq = tid & 15;       // 32 rows x 16 k-quads
        float4 v = ((const float4*)(y + (size_t)row0 * DD))[r * 16 + kq];
        const int rp = r >> 1, hf = r & 1;
        int kb = kq * 4;
        ((float*)&y2[(kb + 0) * Y2P + rp])[hf] = v.x;
        ((float*)&y2[(kb + 1) * Y2P + rp])[hf] = v.y;
        ((float*)&y2[(kb + 2) * Y2P + rp])[hf] = v.z;
        ((float*)&y2[(kb + 3) * Y2P + rp])[hf] = v.w;
    }
    __syncthreads();

    const int rowg = tid & 7;
    const int r0   = rowg * 4;
    const int rp0  = rowg * 2;

    // ---- Phase A: h = tanh(y@W1 + c). 4 rows x 4 j per thread; pairs over rows.
    {
        const int jg = tid >> 3, j0 = jg * 4;        // 64 j-groups x 4 j
        u64 acc[4][2];
        #pragma unroll
        for (int jj = 0; jj < 4; jj++) {
            float c = c_s[j0 + jj];
            u64 cc = pack2(c, c);
            acc[jj][0] = cc; acc[jj][1] = cc;
        }
        #pragma unroll 4
        for (int k = 0; k < DD; k++) {
            ulonglong2 yv = *(const ulonglong2*)&y2[k * Y2P + rp0];  // rows r0..r0+3
            float4 wa = __ldg((const float4*)&W1[k * HH + j0]);
            u64 w0 = pack2(wa.x, wa.x), w1v = pack2(wa.y, wa.y);
            u64 w2v = pack2(wa.z, wa.z), w3 = pack2(wa.w, wa.w);
            acc[0][0] = fma2(yv.x, w0, acc[0][0]); acc[0][1] = fma2(yv.y, w0, acc[0][1]);
            acc[1][0] = fma2(yv.x, w1v, acc[1][0]); acc[1][1] = fma2(yv.y, w1v, acc[1][1]);
            acc[2][0] = fma2(yv.x, w2v, acc[2][0]); acc[2][1] = fma2(yv.y, w2v, acc[2][1]);
            acc[3][0] = fma2(yv.x, w3, acc[3][0]); acc[3][1] = fma2(yv.y, w3, acc[3][1]);
        }
        #pragma unroll
        for (int jj = 0; jj < 4; jj++) {
            float a0, a1, a2, a3;
            unpack2(acc[jj][0], a0, a1);
            unpack2(acc[jj][1], a2, a3);
            ulonglong2 o;
            o.x = pack2(tanh_fast(a0), tanh_fast(a1));
            o.y = pack2(tanh_fast(a2), tanh_fast(a3));
            *(ulonglong2*)&h_s[(j0 + jj) * MT + r0] = o;   // STS.128, conflict-free
        }
    }
    __syncthreads();

    // ---- Phase B: dy = h@W2 + b2. 4 rows x 2 d x 128 j; j-split across halves.
    u64 aB[2][2];
    const int dg = (tid >> 3) & 31, d0 = dg * 2;
    const int jh = tid >> 8;                          // threads 0-255: j 0-127; 256-511: 128-255
    {
        if (jh == 0) {
            u64 v0 = pack2(b2_s[d0],     b2_s[d0]);
            u64 v1 = pack2(b2_s[d0 + 1], b2_s[d0 + 1]);
            aB[0][0] = v0; aB[1][0] = v0;
            aB[0][1] = v1; aB[1][1] = v1;
        } else {
            aB[0][0] = 0; aB[1][0] = 0; aB[0][1] = 0; aB[1][1] = 0;
        }
        const int jbase = jh * 128;
        #pragma unroll 4
        for (int jj = 0; jj < 128; jj++) {
            int j = jbase + jj;
            ulonglong2 hv = *(const ulonglong2*)&h_s[j * MT + r0];   // 1 wf broadcast
            float2 w = __ldg((const float2*)&W2[j * DD + d0]);
            u64 wp0 = pack2(w.x, w.x), wp1 = pack2(w.y, w.y);
            aB[0][0] = fma2(hv.x, wp0, aB[0][0]); aB[1][0] = fma2(hv.y, wp0, aB[1][0]);
            aB[0][1] = fma2(hv.x, wp1, aB[0][1]); aB[1][1] = fma2(hv.y, wp1, aB[1][1]);
        }
        // upper half stores partials into psum (aliases dead y2 buffer: 8KB <= 9KB)
        if (jh == 1) {
            ulonglong2* ps = (ulonglong2*)y2;
            int t1 = tid - 256;
            ps[0 * 256 + t1] = make_ulonglong2(aB[0][0], aB[0][1]);
            ps[1 * 256 + t1] = make_ulonglong2(aB[1][0], aB[1][1]);
        }
    }

    // ---- divergence partials (reads only h_s; overlaps psum drain) ----
    {
        const int r = tid & 31, q = tid >> 5;        // 16 chunks of 16 j
        float g = 0.f;
        #pragma unroll
        for (int jj = 0; jj < 16; jj++) {
            int j = q * 16 + jj;
            float h = h_s[j * MT + r];               // bank = r: conflict-free
            g = fmaf(fmaf(-h, h, 1.0f), s_s[j], g);
        }
        divp[q * MT + r] = g;
    }
    __syncthreads();

    // ---- lower half: reduce j-halves, write dy ----
    if (jh == 0) {
        const ulonglong2* ps = (const ulonglong2*)y2;
        ulonglong2 p0 = ps[0 * 256 + tid];
        ulonglong2 p1 = ps[1 * 256 + tid];
        aB[0][0] = add2(aB[0][0], p0.x); aB[0][1] = add2(aB[0][1], p0.y);
        aB[1][0] = add2(aB[1][0], p1.x); aB[1][1] = add2(aB[1][1], p1.y);
        #pragma unroll
        for (int p = 0; p < 2; p++) {
            float a0, b0, a1, b1v;
            unpack2(aB[p][0], a0, b0);     // (row r, row r+1) at d0
            unpack2(aB[p][1], a1, b1v);    // (row r, row r+1) at d0+1
            size_t base0 = (size_t)(row0 + r0 + 2 * p) * (DD + 1);
            size_t base1 = base0 + (DD + 1);
            out[base0 + d0] = a0; out[base0 + d0 + 1] = a1;
            out[base1 + d0] = b0; out[base1 + d0 + 1] = b1v;
        }
    }

    // ---- divergence final ----
    if (tid < MT) {
        float g = 0.f;
        #pragma unroll
        for (int q = 0; q < 16; q++) g += divp[q * MT + tid];
        out[(size_t)(row0 + tid) * (DD + 1) + DD] = -g;
    }
}

extern "C" void kernel_launch(void* const* d_in, const int* in_sizes, int n_in,
                              void* d_out, int out_size) {
    const float* tt = (const float*)d_in[0];
    const float* y  = (const float*)d_in[1];
    const float* W1 = (const float*)d_in[2];
    const float* b1 = (const float*)d_in[3];
    const float* wt = (const float*)d_in[4];
    const float* W2 = (const float*)d_in[5];
    const float* b2 = (const float*)d_in[6];
    float* out = (float*)d_out;

    ode_prep<<<HH / 32, 128>>>(W1, W2);
    ode_main<<<NN / MT, NT>>>(tt, y, W1, b1, wt, W2, b2, out);
}